// round 15
// baseline (speedup 1.0000x reference)
#include <cuda_runtime.h>
#include <cstdint>
#include <math.h>

// Problem constants
#define PB 8
#define PS 1024
#define PD 768
#define PH 12
#define PDH 64
#define PM 8192          // B*S
#define PNQKV 2304       // 3*D
#define PK 768

// -------- device scratch (allocation-guard-safe) --------
__device__ __align__(16) float g_Wqkv[PNQKV * PK];  // [n][k], tf32-rounded
__device__ __align__(16) float g_Wot[PD * PK];      // [n][k] = Wo[k][n], tf32-rounded
__device__ __align__(16) float g_bqkv[PNQKV];
__device__ __align__(16) float g_xr[PM * PD];       // x, tf32-rounded
__device__ __align__(16) float g_Q[PB * PH * PS * PDH];   // [B,H,S,DH] tf32, pre-scaled
__device__ __align__(16) float g_K[PB * PH * PS * PDH];   // [B,H,S,DH] tf32
__device__ __align__(16) float g_V[PB * PH * PDH * PS];   // [B,H,DH,S'] tf32, kv-permuted
__device__ __align__(16) float g_attn[PM * PD];           // tf32-rounded

__device__ __forceinline__ uint32_t cvt_tf32(float f) {
    uint32_t r; asm("cvt.rna.tf32.f32 %0, %1;" : "=r"(r) : "f"(f)); return r;
}
__device__ __forceinline__ float rndf(float f) { return __uint_as_float(cvt_tf32(f)); }
__device__ __forceinline__ void mma_tf32_16x8x8(float* d, const uint32_t* a, const uint32_t* b) {
    asm volatile(
        "mma.sync.aligned.m16n8k8.row.col.f32.tf32.tf32.f32 "
        "{%0,%1,%2,%3}, {%4,%5,%6,%7}, {%8,%9}, {%0,%1,%2,%3};"
        : "+f"(d[0]), "+f"(d[1]), "+f"(d[2]), "+f"(d[3])
        : "r"(a[0]), "r"(a[1]), "r"(a[2]), "r"(a[3]), "r"(b[0]), "r"(b[1]));
}
__device__ __forceinline__ uint32_t smaddr(const void* p) {
    return (uint32_t)__cvta_generic_to_shared(p);
}
__device__ __forceinline__ void ldm_x4(uint32_t* r, uint32_t a) {
    asm volatile("ldmatrix.sync.aligned.m8n8.x4.shared.b16 {%0,%1,%2,%3}, [%4];"
                 : "=r"(r[0]), "=r"(r[1]), "=r"(r[2]), "=r"(r[3]) : "r"(a));
}
__device__ __forceinline__ void cp16(uint32_t s, const void* g) {
    asm volatile("cp.async.ca.shared.global [%0], [%1], 16;" :: "r"(s), "l"(g));
}
__device__ __forceinline__ void cp_commit() {
    asm volatile("cp.async.commit_group;" ::: "memory");
}
template <int N>
__device__ __forceinline__ void cp_wait() {
    asm volatile("cp.async.wait_group %0;" :: "n"(N) : "memory");
}

// ============================================================
// 1) pack (weights tf32-rounded) + round x
// ============================================================
__global__ void pack_qkv_kernel(const float* __restrict__ Wq, const float* __restrict__ bq,
                                const float* __restrict__ Wk, const float* __restrict__ bk,
                                const float* __restrict__ Wv, const float* __restrict__ bv,
                                const float* __restrict__ Wo) {
    int idx = blockIdx.x * blockDim.x + threadIdx.x;
    if (idx < PNQKV * PK) {
        int n = idx / PK, k = idx % PK;
        int which = n / PD, r = n % PD;
        int h = r >> 6, e = r & 63;
        const float* W = (which == 0) ? Wq : (which == 1) ? Wk : Wv;
        g_Wqkv[idx] = rndf(W[(h * PD + k) * PDH + e]);
    }
    if (idx < PD * PK) {
        int n = idx / PK, k = idx % PK;
        g_Wot[idx] = rndf(Wo[k * PD + n]);
    }
    if (idx < PNQKV) {
        int which = idx / PD, r = idx % PD;
        const float* bb = (which == 0) ? bq : (which == 1) ? bk : bv;
        g_bqkv[idx] = bb[r];
    }
}

__global__ void round_x_kernel(const float* __restrict__ x) {
    int i = blockIdx.x * blockDim.x + threadIdx.x;
    float4 v = *(const float4*)(x + (size_t)i * 4);
    v.x = rndf(v.x); v.y = rndf(v.y); v.z = rndf(v.z); v.w = rndf(v.w);
    *(float4*)(g_xr + (size_t)i * 4) = v;
}

// ============================================================
// 2+4) tf32 mma.sync GEMM: BK=16, 5-stage cp.async pipeline, ldmatrix frags
// ============================================================
#define BM 128
#define BN 128
#define BK 16
#define LST 20
#define NCHUNK (PK / BK)     // 48
#define NSTAGE 5
#define TILEF (BM * LST)     // 2560 floats
#define GEMM_SMEM_BYTES ((NSTAGE * 2 * TILEF + BN) * 4)   // 102912

template <int MODE>
__global__ void __launch_bounds__(256, 2)
mma_gemm_kernel(const float* __restrict__ biasg, float* __restrict__ Cout) {
    extern __shared__ float smg[];
    float* As = smg;
    float* Bs = smg + NSTAGE * TILEF;
    float* sbias = smg + 2 * NSTAGE * TILEF;

    const float* Ap    = (MODE == 0) ? g_xr : g_attn;
    const float* Bp    = (MODE == 0) ? g_Wqkv : g_Wot;
    const float* biasp = (MODE == 0) ? g_bqkv : biasg;

    const int t = threadIdx.x;
    const int warp = t >> 5, lane = t & 31;
    const int wm = warp >> 2;
    const int wn = warp & 3;
    const int g = lane >> 2, ctg = lane & 3;
    const int m0 = blockIdx.y * BM, n0 = blockIdx.x * BN;

    const int lrow0 = t >> 2;
    const int lc4   = (t & 3) << 2;

    const int lr  = lane & 7;
    const int lt1 = (lane >> 3) & 1;
    const int lt2 = lane >> 4;
    const uint32_t As0 = smaddr(As);
    const uint32_t Bs0 = smaddr(Bs);
    const uint32_t a_lane = (uint32_t)(((wm * 64 + lt1 * 8 + lr) * LST + lt2 * 4) * 4);
    const uint32_t b_lane = (uint32_t)(((wn * 32 + lt1 * 8 + lr) * LST + lt2 * 4) * 4);
    const uint32_t a_st = As0 + (uint32_t)((lrow0 * LST + lc4) * 4);
    const uint32_t b_st = Bs0 + (uint32_t)((lrow0 * LST + lc4) * 4);
    const float* a_gl = Ap + (size_t)(m0 + lrow0) * PK + lc4;
    const float* b_gl = Bp + (size_t)(n0 + lrow0) * PK + lc4;

    if (t < BN) sbias[t] = biasp[n0 + t];

    float acc[4][4][4];
#pragma unroll
    for (int i = 0; i < 4; i++)
#pragma unroll
        for (int j = 0; j < 4; j++)
#pragma unroll
            for (int q = 0; q < 4; q++) acc[i][j][q] = 0.f;

#pragma unroll
    for (int s = 0; s < NSTAGE - 1; s++) {
        uint32_t so = (uint32_t)(s * TILEF * 4);
        cp16(a_st + so, a_gl + s * BK);
        cp16(a_st + so + (uint32_t)(64 * LST * 4), a_gl + (size_t)64 * PK + s * BK);
        cp16(b_st + so, b_gl + s * BK);
        cp16(b_st + so + (uint32_t)(64 * LST * 4), b_gl + (size_t)64 * PK + s * BK);
        cp_commit();
    }

    for (int c = 0; c < NCHUNK; c++) {
        cp_wait<NSTAGE - 2>();
        __syncthreads();
        int buf = c % NSTAGE;
        uint32_t abase = As0 + (uint32_t)(buf * TILEF * 4) + a_lane;
        uint32_t bbase = Bs0 + (uint32_t)(buf * TILEF * 4) + b_lane;
#pragma unroll
        for (int s = 0; s < 2; s++) {
            uint32_t koff = (uint32_t)(s * 8 * 4);
            uint32_t af[4][4], bf[4][2];
#pragma unroll
            for (int mt = 0; mt < 4; mt++)
                ldm_x4(af[mt], abase + (uint32_t)(mt * 16 * LST * 4) + koff);
#pragma unroll
            for (int np = 0; np < 2; np++) {
                uint32_t r4[4];
                ldm_x4(r4, bbase + (uint32_t)(np * 16 * LST * 4) + koff);
                bf[2 * np][0] = r4[0]; bf[2 * np + 1][0] = r4[1];
                bf[2 * np][1] = r4[2]; bf[2 * np + 1][1] = r4[3];
            }
#pragma unroll
            for (int mt = 0; mt < 4; mt++)
#pragma unroll
                for (int nt = 0; nt < 4; nt++)
                    mma_tf32_16x8x8(acc[mt][nt], af[mt], bf[nt]);
        }
        int nc = c + NSTAGE - 1;
        if (nc < NCHUNK) {
            int nb = nc % NSTAGE;
            uint32_t so = (uint32_t)(nb * TILEF * 4);
            cp16(a_st + so, a_gl + nc * BK);
            cp16(a_st + so + (uint32_t)(64 * LST * 4), a_gl + (size_t)64 * PK + nc * BK);
            cp16(b_st + so, b_gl + nc * BK);
            cp16(b_st + so + (uint32_t)(64 * LST * 4), b_gl + (size_t)64 * PK + nc * BK);
        }
        cp_commit();
    }

#pragma unroll
    for (int mt = 0; mt < 4; mt++) {
#pragma unroll
        for (int nt = 0; nt < 4; nt++) {
            int row0 = m0 + wm * 64 + mt * 16 + g;
            int cl = wn * 32 + nt * 8 + ctg * 2;
            float2 v0 = make_float2(acc[mt][nt][0] + sbias[cl], acc[mt][nt][1] + sbias[cl + 1]);
            float2 v1 = make_float2(acc[mt][nt][2] + sbias[cl], acc[mt][nt][3] + sbias[cl + 1]);
            if (MODE == 0) {
                int which = n0 / PD;
                float qs = (which == 0) ? 0.125f : 1.0f;
                v0.x = rndf(v0.x * qs); v0.y = rndf(v0.y * qs);
                v1.x = rndf(v1.x * qs); v1.y = rndf(v1.y * qs);
                int r = (n0 % PD) + cl;
                int h = r >> 6, e = r & 63;
                int b0 = row0 >> 10, s0 = row0 & 1023;
                int m1 = row0 + 8;
                int b1 = m1 >> 10, s1 = m1 & 1023;
                if (which == 2) {
                    int s0p = (s0 & ~7) | ((g >> 1) | ((g & 1) << 2));
                    int s1p = s0p + 8;
                    float* dv = g_V;
                    size_t p0 = ((size_t)((b0 * PH + h) * PDH + e)) * PS + s0p;
                    size_t p1 = ((size_t)((b1 * PH + h) * PDH + e)) * PS + s1p;
                    dv[p0] = v0.x; dv[p0 + PS] = v0.y;
                    dv[p1] = v1.x; dv[p1 + PS] = v1.y;
                } else {
                    float* dst = (which == 0) ? g_Q : g_K;
                    *(float2*)(dst + ((size_t)((b0 * PH + h) * PS + s0)) * PDH + e) = v0;
                    *(float2*)(dst + ((size_t)((b1 * PH + h) * PS + s1)) * PDH + e) = v1;
                }
            } else {
                *(float2*)(Cout + (size_t)row0 * PD + n0 + cl) = v0;
                *(float2*)(Cout + (size_t)(row0 + 8) * PD + n0 + cl) = v1;
            }
        }
    }
}

// ============================================================
// 3) Flash attention: static-max softmax, register-resident P,
//    32-row KV tiles DOUBLE-buffered, 3 CTAs/SM, permuted V. (R13, unchanged)
// ============================================================
#define FS 68            // Ps / Ks row stride
#define VS 36            // Vt row stride
#define KSF (32 * FS)
#define VTF (64 * VS)
#define NT 32
#define FA_SMEM_FLOATS (2 * KSF + 2 * VTF + 128 * FS)   // 70656 B

__global__ void __launch_bounds__(128, 3) flash_attn_kernel() {
    extern __shared__ float sm[];
    float* Ks = sm;                       // [2][32][FS]
    float* Vt = sm + 2 * KSF;             // [2][64][VS]
    float* Ps = sm + 2 * KSF + 2 * VTF;   // [128][FS] : Q (pre-scaled tf32)

    const int t = threadIdx.x;
    const int warp = t >> 5, lane = t & 31;
    const int g = lane >> 2, ctg = lane & 3;
    const int bh = blockIdx.y;
    const int q0 = blockIdx.x * 128;
    const int rq = warp * 32;
    const size_t base = (size_t)bh * PS * PDH;

    const int lr  = lane & 7;
    const int lt1 = (lane >> 3) & 1;
    const int lt2 = lane >> 4;
    const uint32_t lane4  = (uint32_t)(((lt1 * 8 + lr) * FS + lt2 * 4) * 4);
    const uint32_t lane4v = (uint32_t)(((lt1 * 8 + lr) * VS + lt2 * 4) * 4);
    const uint32_t Ks0 = smaddr(Ks), Vt0 = smaddr(Vt), Ps0 = smaddr(Ps);
    const uint32_t q_lane0 = Ps0 + (uint32_t)(rq * FS * 4) + lane4;
    const uint32_t q_lane1 = q_lane0 + (uint32_t)(16 * FS * 4);

#pragma unroll
    for (int i = 0; i < 16; i++) {
        int f = t + i * 128;
        int r = f >> 4, c4 = (f & 15) << 2;
        cp16(Ps0 + (uint32_t)((r * FS + c4) * 4),
             g_Q + base + (size_t)(q0 + r) * PDH + c4);
    }
    cp_commit();

#pragma unroll
    for (int i = 0; i < 4; i++) {
        int f = t + i * 128;
        int kv = f >> 4, c4 = (f & 15) << 2;
        cp16(Ks0 + (uint32_t)((kv * FS + c4) * 4),
             g_K + base + (size_t)kv * PDH + c4);
        int dh = f >> 3, c4v = (f & 7) << 2;
        cp16(Vt0 + (uint32_t)((dh * VS + c4v) * 4),
             g_V + base + (size_t)dh * PS + c4v);
    }
    cp_commit();

    float l_p[2][2] = {{0.f, 0.f}, {0.f, 0.f}};
    float o[2][8][4];
#pragma unroll
    for (int mt = 0; mt < 2; mt++)
#pragma unroll
        for (int j = 0; j < 8; j++)
#pragma unroll
            for (int q = 0; q < 4; q++) o[mt][j][q] = 0.f;

    for (int ti = 0; ti < NT; ti++) {
        int buf = ti & 1;
        __syncthreads();
        if (ti < NT - 1) {
            int n1 = (ti + 1) * 32;
            uint32_t ko = (uint32_t)(((buf ^ 1) * KSF) * 4);
            uint32_t vo = (uint32_t)(((buf ^ 1) * VTF) * 4);
#pragma unroll
            for (int i = 0; i < 4; i++) {
                int f = t + i * 128;
                int kv = f >> 4, c4 = (f & 15) << 2;
                cp16(Ks0 + ko + (uint32_t)((kv * FS + c4) * 4),
                     g_K + base + (size_t)(n1 + kv) * PDH + c4);
                int dh = f >> 3, c4v = (f & 7) << 2;
                cp16(Vt0 + vo + (uint32_t)((dh * VS + c4v) * 4),
                     g_V + base + (size_t)dh * PS + n1 + c4v);
            }
            cp_commit();
            cp_wait<1>();
        } else {
            cp_wait<0>();
        }
        __syncthreads();

        uint32_t kbase = Ks0 + (uint32_t)(buf * KSF * 4) + lane4;
        uint32_t vbase = Vt0 + (uint32_t)(buf * VTF * 4) + lane4v;

        float s[2][4][4];
#pragma unroll
        for (int mt = 0; mt < 2; mt++)
#pragma unroll
            for (int j = 0; j < 4; j++)
#pragma unroll
                for (int q = 0; q < 4; q++) s[mt][j][q] = 0.f;

#pragma unroll
        for (int ks = 0; ks < 8; ks++) {
            uint32_t koff = (uint32_t)(ks * 8 * 4);
            uint32_t aq0[4], aq1[4];
            ldm_x4(aq0, q_lane0 + koff);
            ldm_x4(aq1, q_lane1 + koff);
            uint32_t bf[4][2];
#pragma unroll
            for (int jp = 0; jp < 2; jp++) {
                uint32_t r4[4];
                ldm_x4(r4, kbase + (uint32_t)(jp * 16 * FS * 4) + koff);
                bf[2 * jp][0] = r4[0]; bf[2 * jp + 1][0] = r4[1];
                bf[2 * jp][1] = r4[2]; bf[2 * jp + 1][1] = r4[3];
            }
#pragma unroll
            for (int j = 0; j < 4; j++) {
                mma_tf32_16x8x8(s[0][j], aq0, bf[j]);
                mma_tf32_16x8x8(s[1][j], aq1, bf[j]);
            }
        }

#pragma unroll
        for (int mt = 0; mt < 2; mt++)
#pragma unroll
            for (int j = 0; j < 4; j++) {
                float p0 = __expf(s[mt][j][0]);
                float p1 = __expf(s[mt][j][1]);
                float p2 = __expf(s[mt][j][2]);
                float p3 = __expf(s[mt][j][3]);
                s[mt][j][0] = p0; s[mt][j][1] = p1;
                s[mt][j][2] = p2; s[mt][j][3] = p3;
                l_p[mt][0] += p0 + p1;
                l_p[mt][1] += p2 + p3;
            }

#pragma unroll
        for (int j = 0; j < 4; j++) {
            uint32_t joff = (uint32_t)(j * 8 * 4);
            uint32_t bv[8][2];
#pragma unroll
            for (int jp = 0; jp < 4; jp++) {
                uint32_t r4[4];
                ldm_x4(r4, vbase + (uint32_t)(jp * 16 * VS * 4) + joff);
                bv[2 * jp][0] = r4[0]; bv[2 * jp + 1][0] = r4[1];
                bv[2 * jp][1] = r4[2]; bv[2 * jp + 1][1] = r4[3];
            }
            uint32_t ap0[4] = {cvt_tf32(s[0][j][0]), cvt_tf32(s[0][j][2]),
                               cvt_tf32(s[0][j][1]), cvt_tf32(s[0][j][3])};
            uint32_t ap1[4] = {cvt_tf32(s[1][j][0]), cvt_tf32(s[1][j][2]),
                               cvt_tf32(s[1][j][1]), cvt_tf32(s[1][j][3])};
#pragma unroll
            for (int nt = 0; nt < 8; nt++) {
                mma_tf32_16x8x8(o[0][nt], ap0, bv[nt]);
                mma_tf32_16x8x8(o[1][nt], ap1, bv[nt]);
            }
        }
    }

    int b = bh / PH, h = bh % PH;
#pragma unroll
    for (int mt = 0; mt < 2; mt++) {
#pragma unroll
        for (int r = 0; r < 2; r++) {
            l_p[mt][r] += __shfl_xor_sync(0xffffffffu, l_p[mt][r], 1);
            l_p[mt][r] += __shfl_xor_sync(0xffffffffu, l_p[mt][r], 2);
        }
        float inv0 = 1.f / l_p[mt][0], inv1 = 1.f / l_p[mt][1];
        int s0 = q0 + rq + mt * 16 + g, s1 = s0 + 8;
#pragma unroll
        for (int j = 0; j < 8; j++) {
            int e = h * PDH + j * 8 + ctg * 2;
            *(float2*)(g_attn + ((size_t)(b * PS + s0)) * PD + e) =
                make_float2(rndf(o[mt][j][0] * inv0), rndf(o[mt][j][1] * inv0));
            *(float2*)(g_attn + ((size_t)(b * PS + s1)) * PD + e) =
                make_float2(rndf(o[mt][j][2] * inv1), rndf(o[mt][j][3] * inv1));
        }
    }
}

// ============================================================
// launch
// ============================================================
extern "C" void kernel_launch(void* const* d_in, const int* in_sizes, int n_in,
                              void* d_out, int out_size) {
    const float* x  = (const float*)d_in[0];
    const float* Wq = (const float*)d_in[1];
    const float* bq = (const float*)d_in[2];
    const float* Wk = (const float*)d_in[3];
    const float* bk = (const float*)d_in[4];
    const float* Wv = (const float*)d_in[5];
    const float* bv = (const float*)d_in[6];
    const float* Wo = (const float*)d_in[7];
    const float* bo = (const float*)d_in[8];
    float* out = (float*)d_out;

    const int smem_attn = FA_SMEM_FLOATS * (int)sizeof(float);  // 70656
    cudaFuncSetAttribute(flash_attn_kernel,
                         cudaFuncAttributeMaxDynamicSharedMemorySize, smem_attn);
    cudaFuncSetAttribute(mma_gemm_kernel<0>,
                         cudaFuncAttributeMaxDynamicSharedMemorySize, GEMM_SMEM_BYTES);
    cudaFuncSetAttribute(mma_gemm_kernel<1>,
                         cudaFuncAttributeMaxDynamicSharedMemorySize, GEMM_SMEM_BYTES);

    pack_qkv_kernel<<<(PNQKV * PK + 255) / 256, 256>>>(Wq, bq, Wk, bk, Wv, bv, Wo);
    round_x_kernel<<<(PM * PD / 4) / 256, 256>>>(x);

    mma_gemm_kernel<0><<<dim3(PNQKV / 128, PM / 128), 256, GEMM_SMEM_BYTES>>>(nullptr, nullptr);

    flash_attn_kernel<<<dim3(PS / 128, PB * PH), 128, smem_attn>>>();

    mma_gemm_kernel<1><<<dim3(PD / 128, PM / 128), 256, GEMM_SMEM_BYTES>>>(bo, out);
}

// round 17
// speedup vs baseline: 1.1791x; 1.1791x over previous
#include <cuda_runtime.h>
#include <cstdint>
#include <math.h>

// Problem constants
#define PB 8
#define PS 1024
#define PD 768
#define PH 12
#define PDH 64
#define PM 8192          // B*S
#define PNQKV 2304       // 3*D
#define PK 768

// -------- device scratch (allocation-guard-safe) --------
__device__ __align__(16) float g_Wqkv[PNQKV * PK];  // [n][k], tf32-rounded
__device__ __align__(16) float g_Wot[PD * PK];      // [n][k] = Wo[k][n], tf32-rounded
__device__ __align__(16) float g_bqkv[PNQKV];
__device__ __align__(16) float g_Q[PB * PH * PS * PDH];   // [B,H,S,DH] tf32, pre-scaled
__device__ __align__(16) float g_K[PB * PH * PS * PDH];   // [B,H,S,DH] tf32
__device__ __align__(16) float g_V[PB * PH * PDH * PS];   // [B,H,DH,S'] tf32, kv-permuted
__device__ __align__(16) float g_attn[PM * PD];           // tf32-rounded

__device__ __forceinline__ uint32_t cvt_tf32(float f) {
    uint32_t r; asm("cvt.rna.tf32.f32 %0, %1;" : "=r"(r) : "f"(f)); return r;
}
__device__ __forceinline__ float rndf(float f) { return __uint_as_float(cvt_tf32(f)); }
__device__ __forceinline__ void mma_tf32_16x8x8(float* d, const uint32_t* a, const uint32_t* b) {
    asm volatile(
        "mma.sync.aligned.m16n8k8.row.col.f32.tf32.tf32.f32 "
        "{%0,%1,%2,%3}, {%4,%5,%6,%7}, {%8,%9}, {%0,%1,%2,%3};"
        : "+f"(d[0]), "+f"(d[1]), "+f"(d[2]), "+f"(d[3])
        : "r"(a[0]), "r"(a[1]), "r"(a[2]), "r"(a[3]), "r"(b[0]), "r"(b[1]));
}
__device__ __forceinline__ uint32_t smaddr(const void* p) {
    return (uint32_t)__cvta_generic_to_shared(p);
}
__device__ __forceinline__ void ldm_x4(uint32_t* r, uint32_t a) {
    asm volatile("ldmatrix.sync.aligned.m8n8.x4.shared.b16 {%0,%1,%2,%3}, [%4];"
                 : "=r"(r[0]), "=r"(r[1]), "=r"(r[2]), "=r"(r[3]) : "r"(a));
}
__device__ __forceinline__ void cp16(uint32_t s, const void* g) {
    asm volatile("cp.async.ca.shared.global [%0], [%1], 16;" :: "r"(s), "l"(g));
}
__device__ __forceinline__ void cp_commit() {
    asm volatile("cp.async.commit_group;" ::: "memory");
}
template <int N>
__device__ __forceinline__ void cp_wait() {
    asm volatile("cp.async.wait_group %0;" :: "n"(N) : "memory");
}

// ============================================================
// 1) pack (weights tf32-rounded)
// ============================================================
__global__ void pack_qkv_kernel(const float* __restrict__ Wq, const float* __restrict__ bq,
                                const float* __restrict__ Wk, const float* __restrict__ bk,
                                const float* __restrict__ Wv, const float* __restrict__ bv,
                                const float* __restrict__ Wo) {
    int idx = blockIdx.x * blockDim.x + threadIdx.x;
    if (idx < PNQKV * PK) {
        int n = idx / PK, k = idx % PK;
        int which = n / PD, r = n % PD;
        int h = r >> 6, e = r & 63;
        const float* W = (which == 0) ? Wq : (which == 1) ? Wk : Wv;
        g_Wqkv[idx] = rndf(W[(h * PD + k) * PDH + e]);
    }
    if (idx < PD * PK) {
        int n = idx / PK, k = idx % PK;
        g_Wot[idx] = rndf(Wo[k * PD + n]);
    }
    if (idx < PNQKV) {
        int which = idx / PD, r = idx % PD;
        const float* bb = (which == 0) ? bq : (which == 1) ? bk : bv;
        g_bqkv[idx] = bb[r];
    }
}

// ============================================================
// 2+4) tf32 mma.sync GEMM: BK=16, 4-stage cp.async pipeline (R13 config).
//   MODE 0: A = raw x (cvt applied to A-fragments post-ldmatrix).
//   MODE 1: A = g_attn (already tf32-rounded).
// ============================================================
#define BM 128
#define BN 128
#define BK 16
#define LST 20
#define NCHUNK (PK / BK)     // 48
#define NSTAGE 4
#define TILEF (BM * LST)
#define GEMM_SMEM_BYTES ((NSTAGE * 2 * TILEF + BN) * 4)   // 82432

template <int MODE>
__global__ void __launch_bounds__(256, 2)
mma_gemm_kernel(const float* __restrict__ Ain, const float* __restrict__ biasg,
                float* __restrict__ Cout) {
    extern __shared__ float smg[];
    float* As = smg;
    float* Bs = smg + NSTAGE * TILEF;
    float* sbias = smg + 2 * NSTAGE * TILEF;

    const float* Ap    = (MODE == 0) ? Ain : g_attn;
    const float* Bp    = (MODE == 0) ? g_Wqkv : g_Wot;
    const float* biasp = (MODE == 0) ? g_bqkv : biasg;

    const int t = threadIdx.x;
    const int warp = t >> 5, lane = t & 31;
    const int wm = warp >> 2;
    const int wn = warp & 3;
    const int g = lane >> 2, ctg = lane & 3;
    const int m0 = blockIdx.y * BM, n0 = blockIdx.x * BN;

    const int lrow0 = t >> 2;
    const int lc4   = (t & 3) << 2;

    const int lr  = lane & 7;
    const int lt1 = (lane >> 3) & 1;
    const int lt2 = lane >> 4;
    const uint32_t As0 = smaddr(As);
    const uint32_t Bs0 = smaddr(Bs);
    const uint32_t a_lane = (uint32_t)(((wm * 64 + lt1 * 8 + lr) * LST + lt2 * 4) * 4);
    const uint32_t b_lane = (uint32_t)(((wn * 32 + lt1 * 8 + lr) * LST + lt2 * 4) * 4);
    const uint32_t a_st = As0 + (uint32_t)((lrow0 * LST + lc4) * 4);
    const uint32_t b_st = Bs0 + (uint32_t)((lrow0 * LST + lc4) * 4);
    const float* a_gl = Ap + (size_t)(m0 + lrow0) * PK + lc4;
    const float* b_gl = Bp + (size_t)(n0 + lrow0) * PK + lc4;

    if (t < BN) sbias[t] = biasp[n0 + t];

    float acc[4][4][4];
#pragma unroll
    for (int i = 0; i < 4; i++)
#pragma unroll
        for (int j = 0; j < 4; j++)
#pragma unroll
            for (int q = 0; q < 4; q++) acc[i][j][q] = 0.f;

#pragma unroll
    for (int s = 0; s < NSTAGE - 1; s++) {
        uint32_t so = (uint32_t)(s * TILEF * 4);
        cp16(a_st + so, a_gl + s * BK);
        cp16(a_st + so + (uint32_t)(64 * LST * 4), a_gl + (size_t)64 * PK + s * BK);
        cp16(b_st + so, b_gl + s * BK);
        cp16(b_st + so + (uint32_t)(64 * LST * 4), b_gl + (size_t)64 * PK + s * BK);
        cp_commit();
    }

    for (int c = 0; c < NCHUNK; c++) {
        cp_wait<NSTAGE - 2>();
        __syncthreads();
        int buf = c % NSTAGE;
        uint32_t abase = As0 + (uint32_t)(buf * TILEF * 4) + a_lane;
        uint32_t bbase = Bs0 + (uint32_t)(buf * TILEF * 4) + b_lane;
#pragma unroll
        for (int s = 0; s < 2; s++) {
            uint32_t koff = (uint32_t)(s * 8 * 4);
            uint32_t af[4][4], bf[4][2];
#pragma unroll
            for (int mt = 0; mt < 4; mt++) {
                ldm_x4(af[mt], abase + (uint32_t)(mt * 16 * LST * 4) + koff);
                if (MODE == 0) {
#pragma unroll
                    for (int q = 0; q < 4; q++)
                        af[mt][q] = cvt_tf32(__uint_as_float(af[mt][q]));
                }
            }
#pragma unroll
            for (int np = 0; np < 2; np++) {
                uint32_t r4[4];
                ldm_x4(r4, bbase + (uint32_t)(np * 16 * LST * 4) + koff);
                bf[2 * np][0] = r4[0]; bf[2 * np + 1][0] = r4[1];
                bf[2 * np][1] = r4[2]; bf[2 * np + 1][1] = r4[3];
            }
#pragma unroll
            for (int mt = 0; mt < 4; mt++)
#pragma unroll
                for (int nt = 0; nt < 4; nt++)
                    mma_tf32_16x8x8(acc[mt][nt], af[mt], bf[nt]);
        }
        int nc = c + NSTAGE - 1;
        if (nc < NCHUNK) {
            int nb = nc % NSTAGE;
            uint32_t so = (uint32_t)(nb * TILEF * 4);
            cp16(a_st + so, a_gl + nc * BK);
            cp16(a_st + so + (uint32_t)(64 * LST * 4), a_gl + (size_t)64 * PK + nc * BK);
            cp16(b_st + so, b_gl + nc * BK);
            cp16(b_st + so + (uint32_t)(64 * LST * 4), b_gl + (size_t)64 * PK + nc * BK);
        }
        cp_commit();
    }

#pragma unroll
    for (int mt = 0; mt < 4; mt++) {
#pragma unroll
        for (int nt = 0; nt < 4; nt++) {
            int row0 = m0 + wm * 64 + mt * 16 + g;
            int cl = wn * 32 + nt * 8 + ctg * 2;
            float2 v0 = make_float2(acc[mt][nt][0] + sbias[cl], acc[mt][nt][1] + sbias[cl + 1]);
            float2 v1 = make_float2(acc[mt][nt][2] + sbias[cl], acc[mt][nt][3] + sbias[cl + 1]);
            if (MODE == 0) {
                int which = n0 / PD;
                float qs = (which == 0) ? 0.125f : 1.0f;
                v0.x = rndf(v0.x * qs); v0.y = rndf(v0.y * qs);
                v1.x = rndf(v1.x * qs); v1.y = rndf(v1.y * qs);
                int r = (n0 % PD) + cl;
                int h = r >> 6, e = r & 63;
                int b0 = row0 >> 10, s0 = row0 & 1023;
                int m1 = row0 + 8;
                int b1 = m1 >> 10, s1 = m1 & 1023;
                if (which == 2) {
                    int s0p = (s0 & ~7) | ((g >> 1) | ((g & 1) << 2));
                    int s1p = s0p + 8;
                    float* dv = g_V;
                    size_t p0 = ((size_t)((b0 * PH + h) * PDH + e)) * PS + s0p;
                    size_t p1 = ((size_t)((b1 * PH + h) * PDH + e)) * PS + s1p;
                    dv[p0] = v0.x; dv[p0 + PS] = v0.y;
                    dv[p1] = v1.x; dv[p1 + PS] = v1.y;
                } else {
                    float* dst = (which == 0) ? g_Q : g_K;
                    *(float2*)(dst + ((size_t)((b0 * PH + h) * PS + s0)) * PDH + e) = v0;
                    *(float2*)(dst + ((size_t)((b1 * PH + h) * PS + s1)) * PDH + e) = v1;
                }
            } else {
                *(float2*)(Cout + (size_t)row0 * PD + n0 + cl) = v0;
                *(float2*)(Cout + (size_t)(row0 + 8) * PD + n0 + cl) = v1;
            }
        }
    }
}

// ============================================================
// 3) Flash attention: static-max softmax, register-resident P,
//    32-row KV tiles DOUBLE-buffered, 3 CTAs/SM, permuted V. (R13, unchanged)
// ============================================================
#define FS 68            // Ps / Ks row stride
#define VS 36            // Vt row stride
#define KSF (32 * FS)
#define VTF (64 * VS)
#define NT 32
#define FA_SMEM_FLOATS (2 * KSF + 2 * VTF + 128 * FS)   // 70656 B

__global__ void __launch_bounds__(128, 3) flash_attn_kernel() {
    extern __shared__ float sm[];
    float* Ks = sm;                       // [2][32][FS]
    float* Vt = sm + 2 * KSF;             // [2][64][VS]
    float* Ps = sm + 2 * KSF + 2 * VTF;   // [128][FS] : Q (pre-scaled tf32)

    const int t = threadIdx.x;
    const int warp = t >> 5, lane = t & 31;
    const int g = lane >> 2, ctg = lane & 3;
    const int bh = blockIdx.y;
    const int q0 = blockIdx.x * 128;
    const int rq = warp * 32;
    const size_t base = (size_t)bh * PS * PDH;

    const int lr  = lane & 7;
    const int lt1 = (lane >> 3) & 1;
    const int lt2 = lane >> 4;
    const uint32_t lane4  = (uint32_t)(((lt1 * 8 + lr) * FS + lt2 * 4) * 4);
    const uint32_t lane4v = (uint32_t)(((lt1 * 8 + lr) * VS + lt2 * 4) * 4);
    const uint32_t Ks0 = smaddr(Ks), Vt0 = smaddr(Vt), Ps0 = smaddr(Ps);
    const uint32_t q_lane0 = Ps0 + (uint32_t)(rq * FS * 4) + lane4;
    const uint32_t q_lane1 = q_lane0 + (uint32_t)(16 * FS * 4);

#pragma unroll
    for (int i = 0; i < 16; i++) {
        int f = t + i * 128;
        int r = f >> 4, c4 = (f & 15) << 2;
        cp16(Ps0 + (uint32_t)((r * FS + c4) * 4),
             g_Q + base + (size_t)(q0 + r) * PDH + c4);
    }
    cp_commit();

#pragma unroll
    for (int i = 0; i < 4; i++) {
        int f = t + i * 128;
        int kv = f >> 4, c4 = (f & 15) << 2;
        cp16(Ks0 + (uint32_t)((kv * FS + c4) * 4),
             g_K + base + (size_t)kv * PDH + c4);
        int dh = f >> 3, c4v = (f & 7) << 2;
        cp16(Vt0 + (uint32_t)((dh * VS + c4v) * 4),
             g_V + base + (size_t)dh * PS + c4v);
    }
    cp_commit();

    float l_p[2][2] = {{0.f, 0.f}, {0.f, 0.f}};
    float o[2][8][4];
#pragma unroll
    for (int mt = 0; mt < 2; mt++)
#pragma unroll
        for (int j = 0; j < 8; j++)
#pragma unroll
            for (int q = 0; q < 4; q++) o[mt][j][q] = 0.f;

    for (int ti = 0; ti < NT; ti++) {
        int buf = ti & 1;
        __syncthreads();
        if (ti < NT - 1) {
            int n1 = (ti + 1) * 32;
            uint32_t ko = (uint32_t)(((buf ^ 1) * KSF) * 4);
            uint32_t vo = (uint32_t)(((buf ^ 1) * VTF) * 4);
#pragma unroll
            for (int i = 0; i < 4; i++) {
                int f = t + i * 128;
                int kv = f >> 4, c4 = (f & 15) << 2;
                cp16(Ks0 + ko + (uint32_t)((kv * FS + c4) * 4),
                     g_K + base + (size_t)(n1 + kv) * PDH + c4);
                int dh = f >> 3, c4v = (f & 7) << 2;
                cp16(Vt0 + vo + (uint32_t)((dh * VS + c4v) * 4),
                     g_V + base + (size_t)dh * PS + n1 + c4v);
            }
            cp_commit();
            cp_wait<1>();
        } else {
            cp_wait<0>();
        }
        __syncthreads();

        uint32_t kbase = Ks0 + (uint32_t)(buf * KSF * 4) + lane4;
        uint32_t vbase = Vt0 + (uint32_t)(buf * VTF * 4) + lane4v;

        float s[2][4][4];
#pragma unroll
        for (int mt = 0; mt < 2; mt++)
#pragma unroll
            for (int j = 0; j < 4; j++)
#pragma unroll
                for (int q = 0; q < 4; q++) s[mt][j][q] = 0.f;

#pragma unroll
        for (int ks = 0; ks < 8; ks++) {
            uint32_t koff = (uint32_t)(ks * 8 * 4);
            uint32_t aq0[4], aq1[4];
            ldm_x4(aq0, q_lane0 + koff);
            ldm_x4(aq1, q_lane1 + koff);
            uint32_t bf[4][2];
#pragma unroll
            for (int jp = 0; jp < 2; jp++) {
                uint32_t r4[4];
                ldm_x4(r4, kbase + (uint32_t)(jp * 16 * FS * 4) + koff);
                bf[2 * jp][0] = r4[0]; bf[2 * jp + 1][0] = r4[1];
                bf[2 * jp][1] = r4[2]; bf[2 * jp + 1][1] = r4[3];
            }
#pragma unroll
            for (int j = 0; j < 4; j++) {
                mma_tf32_16x8x8(s[0][j], aq0, bf[j]);
                mma_tf32_16x8x8(s[1][j], aq1, bf[j]);
            }
        }

#pragma unroll
        for (int mt = 0; mt < 2; mt++)
#pragma unroll
            for (int j = 0; j < 4; j++) {
                float p0 = __expf(s[mt][j][0]);
                float p1 = __expf(s[mt][j][1]);
                float p2 = __expf(s[mt][j][2]);
                float p3 = __expf(s[mt][j][3]);
                s[mt][j][0] = p0; s[mt][j][1] = p1;
                s[mt][j][2] = p2; s[mt][j][3] = p3;
                l_p[mt][0] += p0 + p1;
                l_p[mt][1] += p2 + p3;
            }

#pragma unroll
        for (int j = 0; j < 4; j++) {
            uint32_t joff = (uint32_t)(j * 8 * 4);
            uint32_t bv[8][2];
#pragma unroll
            for (int jp = 0; jp < 4; jp++) {
                uint32_t r4[4];
                ldm_x4(r4, vbase + (uint32_t)(jp * 16 * VS * 4) + joff);
                bv[2 * jp][0] = r4[0]; bv[2 * jp + 1][0] = r4[1];
                bv[2 * jp][1] = r4[2]; bv[2 * jp + 1][1] = r4[3];
            }
            uint32_t ap0[4] = {cvt_tf32(s[0][j][0]), cvt_tf32(s[0][j][2]),
                               cvt_tf32(s[0][j][1]), cvt_tf32(s[0][j][3])};
            uint32_t ap1[4] = {cvt_tf32(s[1][j][0]), cvt_tf32(s[1][j][2]),
                               cvt_tf32(s[1][j][1]), cvt_tf32(s[1][j][3])};
#pragma unroll
            for (int nt = 0; nt < 8; nt++) {
                mma_tf32_16x8x8(o[0][nt], ap0, bv[nt]);
                mma_tf32_16x8x8(o[1][nt], ap1, bv[nt]);
            }
        }
    }

    int b = bh / PH, h = bh % PH;
#pragma unroll
    for (int mt = 0; mt < 2; mt++) {
#pragma unroll
        for (int r = 0; r < 2; r++) {
            l_p[mt][r] += __shfl_xor_sync(0xffffffffu, l_p[mt][r], 1);
            l_p[mt][r] += __shfl_xor_sync(0xffffffffu, l_p[mt][r], 2);
        }
        float inv0 = 1.f / l_p[mt][0], inv1 = 1.f / l_p[mt][1];
        int s0 = q0 + rq + mt * 16 + g, s1 = s0 + 8;
#pragma unroll
        for (int j = 0; j < 8; j++) {
            int e = h * PDH + j * 8 + ctg * 2;
            *(float2*)(g_attn + ((size_t)(b * PS + s0)) * PD + e) =
                make_float2(rndf(o[mt][j][0] * inv0), rndf(o[mt][j][1] * inv0));
            *(float2*)(g_attn + ((size_t)(b * PS + s1)) * PD + e) =
                make_float2(rndf(o[mt][j][2] * inv1), rndf(o[mt][j][3] * inv1));
        }
    }
}

// ============================================================
// launch
// ============================================================
extern "C" void kernel_launch(void* const* d_in, const int* in_sizes, int n_in,
                              void* d_out, int out_size) {
    const float* x  = (const float*)d_in[0];
    const float* Wq = (const float*)d_in[1];
    const float* bq = (const float*)d_in[2];
    const float* Wk = (const float*)d_in[3];
    const float* bk = (const float*)d_in[4];
    const float* Wv = (const float*)d_in[5];
    const float* bv = (const float*)d_in[6];
    const float* Wo = (const float*)d_in[7];
    const float* bo = (const float*)d_in[8];
    float* out = (float*)d_out;

    const int smem_attn = FA_SMEM_FLOATS * (int)sizeof(float);  // 70656
    cudaFuncSetAttribute(flash_attn_kernel,
                         cudaFuncAttributeMaxDynamicSharedMemorySize, smem_attn);
    cudaFuncSetAttribute(mma_gemm_kernel<0>,
                         cudaFuncAttributeMaxDynamicSharedMemorySize, GEMM_SMEM_BYTES);
    cudaFuncSetAttribute(mma_gemm_kernel<1>,
                         cudaFuncAttributeMaxDynamicSharedMemorySize, GEMM_SMEM_BYTES);

    pack_qkv_kernel<<<(PNQKV * PK + 255) / 256, 256>>>(Wq, bq, Wk, bk, Wv, bv, Wo);

    mma_gemm_kernel<0><<<dim3(PNQKV / 128, PM / 128), 256, GEMM_SMEM_BYTES>>>(x, nullptr, nullptr);

    flash_attn_kernel<<<dim3(PS / 128, PB * PH), 128, smem_attn>>>();

    mma_gemm_kernel<1><<<dim3(PD / 128, PM / 128), 256, GEMM_SMEM_BYTES>>>(nullptr, bo, out);
}